// round 6
// baseline (speedup 1.0000x reference)
#include <cuda_runtime.h>

#define BATCH    8
#define NPTS     4096
#define THREADS  128
#define TI       16                      // thread-grid rows
#define TJ       8                       // thread-grid cols
#define RPT      8                       // rows per thread
#define RPAIRS   (RPT / 2)               // 4 packed row pairs
#define CPT      32                      // cols per thread
#define ROWTILE  128                     // rows per block
#define COLTILE  256                     // cols per block
#define NROWT    (NPTS / ROWTILE)        // 32 row tiles
#define NCOLS    (NPTS / COLTILE)        // 16 col splits
#define NBLK     (BATCH * NROWT * NCOLS) // 4096 blocks
#define NQ       (2 * BATCH * NPTS)      // 65536 result slots
#define RBLK     256                     // reduce blocks
#define CSTRIDE  (2 * CPT + 1)           // padded smem stride per tj (bank stagger)

__device__ unsigned g_max[NQ];   // reversed order keys; 0 == +inf identity
__device__ float    g_bsum[RBLK];
__device__ unsigned g_tick;      // zero-init; self-reset each replay

// ---- f32x2 helpers -------------------------------------------------------
__device__ __forceinline__ unsigned long long pk(float lo, float hi) {
    unsigned long long r;
    asm("mov.b64 %0, {%1, %2};" : "=l"(r)
        : "r"(__float_as_uint(lo)), "r"(__float_as_uint(hi)));
    return r;
}
__device__ __forceinline__ unsigned long long fma2(
    unsigned long long a, unsigned long long b, unsigned long long c) {
    unsigned long long d;
    asm("fma.rn.f32x2 %0, %1, %2, %3;" : "=l"(d) : "l"(a), "l"(b), "l"(c));
    return d;
}
__device__ __forceinline__ unsigned long long add2(
    unsigned long long a, unsigned long long b) {
    unsigned long long d;
    asm("add.rn.f32x2 %0, %1, %2;" : "=l"(d) : "l"(a), "l"(b));
    return d;
}
__device__ __forceinline__ void unpk(unsigned long long v, float& lo, float& hi) {
    unsigned a, b;
    asm("mov.b64 {%0, %1}, %2;" : "=r"(a), "=r"(b) : "l"(v));
    lo = __uint_as_float(a);
    hi = __uint_as_float(b);
}

// order-preserving float->uint key, REVERSED (smaller float -> larger key)
// so zero-initialized g_max is the identity for atomicMax
__device__ __forceinline__ unsigned rkey(float f) {
    unsigned u = __float_as_uint(f);
    unsigned k = (u >> 31) ? ~u : (u | 0x80000000u);
    return ~k;
}
__device__ __forceinline__ float rdecode(unsigned r) {
    unsigned k = ~r;
    unsigned u = (k >> 31) ? (k & 0x7FFFFFFFu) : ~k;
    return __uint_as_float(u);
}

// ---- kernel 1: fused both-direction tile kernel --------------------------
// Computes D once per (row,col) pair; extracts row mins AND col mins.
__global__ __launch_bounds__(THREADS, 4)
void chamfer_kernel(const float* __restrict__ pred,
                    const float* __restrict__ target)
{
    // per-col duplicated quads: [tj][2*local+0]=(t2,t2|-2x,-2x), [.. +1]=(-2y,-2y|-2z,-2z)
    __shared__ ulonglong2 colbuf[TJ * CSTRIDE];   // ~8.3 KB
    __shared__ unsigned   rowkey[ROWTILE];
    __shared__ unsigned   colkey[COLTILE];

    int bid = blockIdx.x;
    int cs  = bid & (NCOLS - 1);
    int rt  = (bid >> 4) & (NROWT - 1);
    int b   = bid >> 9;

    int tid = threadIdx.x;
    int tj  = tid & (TJ - 1);
    int ti  = tid >> 3;

    rowkey[tid] = 0u;
    colkey[tid] = 0u;
    colkey[tid + THREADS] = 0u;

    // stage 2 cols per thread into padded smem
    {
        int c0 = tid * 2;
        const float2* p = (const float2*)(target + ((size_t)b * NPTS + cs * COLTILE + c0) * 3);
        float2 f0 = p[0], f1 = p[1], f2 = p[2];
        float x0 = f0.x, y0 = f0.y, z0 = f1.x;
        float x1 = f1.y, y1 = f2.x, z1 = f2.y;
        float t20 = x0 * x0 + y0 * y0 + z0 * z0;
        float t21 = x1 * x1 + y1 * y1 + z1 * z1;
        int o0 = (c0 / CPT) * CSTRIDE + 2 * (c0 % CPT);
        int o1 = ((c0 + 1) / CPT) * CSTRIDE + 2 * ((c0 + 1) % CPT);
        colbuf[o0 + 0] = make_ulonglong2(pk(t20, t20), pk(-2.f * x0, -2.f * x0));
        colbuf[o0 + 1] = make_ulonglong2(pk(-2.f * y0, -2.f * y0), pk(-2.f * z0, -2.f * z0));
        colbuf[o1 + 0] = make_ulonglong2(pk(t21, t21), pk(-2.f * x1, -2.f * x1));
        colbuf[o1 + 1] = make_ulonglong2(pk(-2.f * y1, -2.f * y1), pk(-2.f * z1, -2.f * z1));
    }

    // load this thread's 8 rows (pred points), packed two-rows-per-register
    int rbase = rt * ROWTILE + ti * RPT;
    const float* rb = pred + ((size_t)b * NPTS + rbase) * 3;
    unsigned long long pxp[RPAIRS], pyp[RPAIRS], pzp[RPAIRS], p2p[RPAIRS];
    #pragma unroll
    for (int rp = 0; rp < RPAIRS; rp++) {
        float x0 = rb[6 * rp + 0], y0 = rb[6 * rp + 1], z0 = rb[6 * rp + 2];
        float x1 = rb[6 * rp + 3], y1 = rb[6 * rp + 4], z1 = rb[6 * rp + 5];
        pxp[rp] = pk(x0, x1);
        pyp[rp] = pk(y0, y1);
        pzp[rp] = pk(z0, z1);
        p2p[rp] = pk(x0 * x0 + y0 * y0 + z0 * z0,
                     x1 * x1 + y1 * y1 + z1 * z1);
    }
    __syncthreads();

    float rlo[RPAIRS], rhi[RPAIRS];
    #pragma unroll
    for (int rp = 0; rp < RPAIRS; rp++) { rlo[rp] = 3.0e38f; rhi[rp] = 3.0e38f; }
    float cmin[CPT];
    #pragma unroll
    for (int cc = 0; cc < CPT; cc++) cmin[cc] = 3.0e38f;

    int cb = tj * CSTRIDE;
    #pragma unroll
    for (int cc = 0; cc < CPT; cc++) {
        ulonglong2 a  = colbuf[cb + 2 * cc + 0];   // (t2 dup, -2x dup)
        ulonglong2 bb = colbuf[cb + 2 * cc + 1];   // (-2y dup, -2z dup)
        #pragma unroll
        for (int rp = 0; rp < RPAIRS; rp++) {
            unsigned long long v =
                fma2(bb.y, pzp[rp],
                fma2(bb.x, pyp[rp],
                fma2(a.y,  pxp[rp], add2(a.x, p2p[rp]))));
            float lo, hi;
            unpk(v, lo, hi);
            rlo[rp]  = fminf(rlo[rp], lo);
            rhi[rp]  = fminf(rhi[rp], hi);
            cmin[cc] = fminf(cmin[cc], fminf(lo, hi));
        }
    }

    // in-block combine (smem atomics on reversed keys, identity 0)
    #pragma unroll
    for (int rp = 0; rp < RPAIRS; rp++) {
        atomicMax(&rowkey[ti * RPT + 2 * rp + 0], rkey(rlo[rp]));
        atomicMax(&rowkey[ti * RPT + 2 * rp + 1], rkey(rhi[rp]));
    }
    #pragma unroll
    for (int cc = 0; cc < CPT; cc++)
        atomicMax(&colkey[tj * CPT + cc], rkey(cmin[cc]));
    __syncthreads();

    // flush to global (rows: pred->target mins; cols: target->pred mins)
    atomicMax(&g_max[b * NPTS + rt * ROWTILE + tid], rowkey[tid]);
    atomicMax(&g_max[(BATCH + b) * NPTS + cs * COLTILE + tid], colkey[tid]);
    atomicMax(&g_max[(BATCH + b) * NPTS + cs * COLTILE + THREADS + tid],
              colkey[tid + THREADS]);
}

// ---- kernel 2: decode + sum + self-reset + ticket finish -----------------
__global__ __launch_bounds__(256)
void reduce_kernel(float* __restrict__ out)
{
    __shared__ float wsum[8];
    __shared__ int   is_last;
    int tid = threadIdx.x;
    int i   = blockIdx.x * 256 + tid;

    unsigned k = g_max[i];
    g_max[i] = 0u;   // reset for next graph replay

    float sum = rdecode(k);

    #pragma unroll
    for (int off = 16; off > 0; off >>= 1)
        sum += __shfl_down_sync(0xffffffffu, sum, off);
    if ((tid & 31) == 0) wsum[tid >> 5] = sum;
    __syncthreads();

    if (tid == 0) {
        float s = 0.0f;
        #pragma unroll
        for (int w = 0; w < 8; w++) s += wsum[w];
        g_bsum[blockIdx.x] = s;
        __threadfence();
        unsigned t = atomicAdd(&g_tick, 1u);
        is_last = (t == RBLK - 1);
    }
    __syncthreads();

    if (is_last && tid < 32) {
        __threadfence();
        float s = 0.0f;
        #pragma unroll
        for (int r = 0; r < RBLK / 32; r++)
            s += *((volatile float*)&g_bsum[r * 32 + tid]);
        #pragma unroll
        for (int off = 16; off > 0; off >>= 1)
            s += __shfl_down_sync(0xffffffffu, s, off);
        if (tid == 0) {
            out[0] = s * (1.0f / (float)(BATCH * NPTS));
            g_tick = 0;   // self-reset for next graph replay
        }
    }
}

extern "C" void kernel_launch(void* const* d_in, const int* in_sizes, int n_in,
                              void* d_out, int out_size)
{
    const float* pred   = (const float*)d_in[0];
    const float* target = (const float*)d_in[1];
    float* out = (float*)d_out;

    chamfer_kernel<<<NBLK, THREADS>>>(pred, target);
    reduce_kernel<<<RBLK, 256>>>(out);
}

// round 7
// speedup vs baseline: 2.1661x; 2.1661x over previous
#include <cuda_runtime.h>

#define BATCH    8
#define NPTS     4096
#define THREADS  128
#define TI       16                      // thread-grid rows
#define TJ       8                       // thread-grid cols
#define RPT      8                       // rows per thread
#define RPAIRS   (RPT / 2)               // 4 packed row pairs
#define CPT      32                      // cols per thread
#define ROWTILE  128                     // rows per block
#define COLTILE  256                     // cols per block
#define NROWT    (NPTS / ROWTILE)        // 32 row tiles
#define NCOLS    (NPTS / COLTILE)        // 16 col splits
#define NBLK     (BATCH * NROWT * NCOLS) // 4096 blocks
#define NQ       (2 * BATCH * NPTS)      // 65536 result slots
#define RBLK     64                      // reduce blocks
#define CSTRIDE  (2 * CPT + 1)           // padded smem stride per tj

__device__ unsigned g_max[NQ];   // reversed order keys; 0 == +inf identity
__device__ float    g_bsum[RBLK];
__device__ unsigned g_tick;      // zero-init; self-reset each replay

// ---- f32x2 helpers -------------------------------------------------------
__device__ __forceinline__ unsigned long long pk(float lo, float hi) {
    unsigned long long r;
    asm("mov.b64 %0, {%1, %2};" : "=l"(r)
        : "r"(__float_as_uint(lo)), "r"(__float_as_uint(hi)));
    return r;
}
__device__ __forceinline__ unsigned long long fma2(
    unsigned long long a, unsigned long long b, unsigned long long c) {
    unsigned long long d;
    asm("fma.rn.f32x2 %0, %1, %2, %3;" : "=l"(d) : "l"(a), "l"(b), "l"(c));
    return d;
}
__device__ __forceinline__ unsigned long long add2(
    unsigned long long a, unsigned long long b) {
    unsigned long long d;
    asm("add.rn.f32x2 %0, %1, %2;" : "=l"(d) : "l"(a), "l"(b));
    return d;
}
__device__ __forceinline__ void unpk(unsigned long long v, float& lo, float& hi) {
    unsigned a, b;
    asm("mov.b64 {%0, %1}, %2;" : "=r"(a), "=r"(b) : "l"(v));
    lo = __uint_as_float(a);
    hi = __uint_as_float(b);
}

// order-preserving float->uint key, REVERSED (smaller float -> larger key)
__device__ __forceinline__ unsigned rkey(float f) {
    unsigned u = __float_as_uint(f);
    unsigned k = (u >> 31) ? ~u : (u | 0x80000000u);
    return ~k;
}
__device__ __forceinline__ float rdecode(unsigned r) {
    unsigned k = ~r;
    unsigned u = (k >> 31) ? (k & 0x7FFFFFFFu) : ~k;
    return __uint_as_float(u);
}

// ---- kernel 1: fused both-direction tile kernel, shuffle epilogue --------
__global__ __launch_bounds__(THREADS, 4)
void chamfer_kernel(const float* __restrict__ pred,
                    const float* __restrict__ target)
{
    __shared__ ulonglong2 colbuf[TJ * CSTRIDE];     // ~8.3 KB candidate quads
    __shared__ float      colpart[4 * COLTILE];     // 4 KB per-warp col partials

    int bid = blockIdx.x;
    int cs  = bid & (NCOLS - 1);
    int rt  = (bid >> 4) & (NROWT - 1);
    int b   = bid >> 9;

    int tid = threadIdx.x;
    int tj  = tid & (TJ - 1);
    int ti  = tid >> 3;
    int wid = tid >> 5;

    // stage 2 cols per thread into padded smem (duplicated lanes for f32x2)
    {
        int c0 = tid * 2;
        const float2* p = (const float2*)(target + ((size_t)b * NPTS + cs * COLTILE + c0) * 3);
        float2 f0 = p[0], f1 = p[1], f2 = p[2];
        float x0 = f0.x, y0 = f0.y, z0 = f1.x;
        float x1 = f1.y, y1 = f2.x, z1 = f2.y;
        float t20 = x0 * x0 + y0 * y0 + z0 * z0;
        float t21 = x1 * x1 + y1 * y1 + z1 * z1;
        int o0 = (c0 / CPT) * CSTRIDE + 2 * (c0 % CPT);
        int o1 = ((c0 + 1) / CPT) * CSTRIDE + 2 * ((c0 + 1) % CPT);
        colbuf[o0 + 0] = make_ulonglong2(pk(t20, t20), pk(-2.f * x0, -2.f * x0));
        colbuf[o0 + 1] = make_ulonglong2(pk(-2.f * y0, -2.f * y0), pk(-2.f * z0, -2.f * z0));
        colbuf[o1 + 0] = make_ulonglong2(pk(t21, t21), pk(-2.f * x1, -2.f * x1));
        colbuf[o1 + 1] = make_ulonglong2(pk(-2.f * y1, -2.f * y1), pk(-2.f * z1, -2.f * z1));
    }

    // load this thread's 8 rows (pred points), packed two-rows-per-register
    int rbase = rt * ROWTILE + ti * RPT;
    const float* rb = pred + ((size_t)b * NPTS + rbase) * 3;
    unsigned long long pxp[RPAIRS], pyp[RPAIRS], pzp[RPAIRS], p2p[RPAIRS];
    #pragma unroll
    for (int rp = 0; rp < RPAIRS; rp++) {
        float x0 = rb[6 * rp + 0], y0 = rb[6 * rp + 1], z0 = rb[6 * rp + 2];
        float x1 = rb[6 * rp + 3], y1 = rb[6 * rp + 4], z1 = rb[6 * rp + 5];
        pxp[rp] = pk(x0, x1);
        pyp[rp] = pk(y0, y1);
        pzp[rp] = pk(z0, z1);
        p2p[rp] = pk(x0 * x0 + y0 * y0 + z0 * z0,
                     x1 * x1 + y1 * y1 + z1 * z1);
    }
    __syncthreads();

    float rlo[RPAIRS], rhi[RPAIRS];
    #pragma unroll
    for (int rp = 0; rp < RPAIRS; rp++) { rlo[rp] = 3.0e38f; rhi[rp] = 3.0e38f; }
    float cmin[CPT];
    #pragma unroll
    for (int cc = 0; cc < CPT; cc++) cmin[cc] = 3.0e38f;

    int cb = tj * CSTRIDE;
    #pragma unroll
    for (int cc = 0; cc < CPT; cc++) {
        ulonglong2 a  = colbuf[cb + 2 * cc + 0];   // (t2 dup, -2x dup)
        ulonglong2 bb = colbuf[cb + 2 * cc + 1];   // (-2y dup, -2z dup)
        #pragma unroll
        for (int rp = 0; rp < RPAIRS; rp++) {
            unsigned long long v =
                fma2(bb.y, pzp[rp],
                fma2(bb.x, pyp[rp],
                fma2(a.y,  pxp[rp], add2(a.x, p2p[rp]))));
            float lo, hi;
            unpk(v, lo, hi);
            rlo[rp]  = fminf(rlo[rp], lo);
            rhi[rp]  = fminf(rhi[rp], hi);
            cmin[cc] = fminf(cmin[cc], fminf(lo, hi));
        }
    }

    // ---- row mins: shuffle-reduce across tj (lane bits 0-2), no atomics --
    unsigned rowq = b * NPTS + rt * ROWTILE + ti * RPT;
    #pragma unroll
    for (int rp = 0; rp < RPAIRS; rp++) {
        float lo = rlo[rp], hi = rhi[rp];
        #pragma unroll
        for (int m = 1; m < 8; m <<= 1) {
            lo = fminf(lo, __shfl_xor_sync(0xffffffffu, lo, m));
            hi = fminf(hi, __shfl_xor_sync(0xffffffffu, hi, m));
        }
        if (tj == 0) {
            atomicMax(&g_max[rowq + 2 * rp + 0], rkey(lo));
            atomicMax(&g_max[rowq + 2 * rp + 1], rkey(hi));
        }
    }

    // ---- col mins: shuffle-reduce across in-warp ti (lane bits 3-4) ------
    #pragma unroll
    for (int cc = 0; cc < CPT; cc++) {
        float v = cmin[cc];
        v = fminf(v, __shfl_xor_sync(0xffffffffu, v, 8));
        v = fminf(v, __shfl_xor_sync(0xffffffffu, v, 16));
        cmin[cc] = v;
    }
    if ((tid & 24) == 0) {   // lanes 0..7 of each warp hold warp-level col mins
        #pragma unroll
        for (int cc = 0; cc < CPT; cc++)
            colpart[wid * COLTILE + tj * CPT + cc] = cmin[cc];
    }
    __syncthreads();

    // combine 4 warp partials; 2 cols per thread
    {
        int c = tid * 2;
        float v0 = fminf(fminf(colpart[c],               colpart[COLTILE + c]),
                         fminf(colpart[2 * COLTILE + c], colpart[3 * COLTILE + c]));
        float v1 = fminf(fminf(colpart[c + 1],               colpart[COLTILE + c + 1]),
                         fminf(colpart[2 * COLTILE + c + 1], colpart[3 * COLTILE + c + 1]));
        unsigned colq = (BATCH + b) * NPTS + cs * COLTILE + c;
        atomicMax(&g_max[colq + 0], rkey(v0));
        atomicMax(&g_max[colq + 1], rkey(v1));
    }
}

// ---- kernel 2: decode + sum + self-reset + ticket finish -----------------
__global__ __launch_bounds__(256)
void reduce_kernel(float* __restrict__ out)
{
    __shared__ float wsum[8];
    __shared__ int   is_last;
    int tid = threadIdx.x;
    int i4  = (blockIdx.x * 256 + tid) * 4;

    uint4 k = *(const uint4*)&g_max[i4];
    *(uint4*)&g_max[i4] = make_uint4(0u, 0u, 0u, 0u);   // reset for replay

    float sum = (rdecode(k.x) + rdecode(k.y)) + (rdecode(k.z) + rdecode(k.w));

    #pragma unroll
    for (int off = 16; off > 0; off >>= 1)
        sum += __shfl_down_sync(0xffffffffu, sum, off);
    if ((tid & 31) == 0) wsum[tid >> 5] = sum;
    __syncthreads();

    if (tid == 0) {
        float s = 0.0f;
        #pragma unroll
        for (int w = 0; w < 8; w++) s += wsum[w];
        g_bsum[blockIdx.x] = s;
        __threadfence();
        unsigned t = atomicAdd(&g_tick, 1u);
        is_last = (t == RBLK - 1);
    }
    __syncthreads();

    if (is_last && tid < 32) {
        __threadfence();
        float s = 0.0f;
        #pragma unroll
        for (int r = 0; r < RBLK / 32; r++)
            s += *((volatile float*)&g_bsum[r * 32 + tid]);
        #pragma unroll
        for (int off = 16; off > 0; off >>= 1)
            s += __shfl_down_sync(0xffffffffu, s, off);
        if (tid == 0) {
            out[0] = s * (1.0f / (float)(BATCH * NPTS));
            g_tick = 0;   // self-reset for next graph replay
        }
    }
}

extern "C" void kernel_launch(void* const* d_in, const int* in_sizes, int n_in,
                              void* d_out, int out_size)
{
    const float* pred   = (const float*)d_in[0];
    const float* target = (const float*)d_in[1];
    float* out = (float*)d_out;

    chamfer_kernel<<<NBLK, THREADS>>>(pred, target);
    reduce_kernel<<<RBLK, 256>>>(out);
}